// round 1
// baseline (speedup 1.0000x reference)
#include <cuda_runtime.h>
#include <cuda_bf16.h>

// Matvec: out[n] = sum_d fc[n][d] * input[d],  n < 50, d < 1048576.
// DRAM-bound: 200 MB of fc streamed once, 4 MB input (L2-resident).
//
// Stage 1: grid (NCHUNK x N_ROWS). Each block reduces a contiguous chunk of
//          one row's dot product into g_partials[row][chunk].
// Stage 2: 50 blocks x 32 threads, warp-reduce the NCHUNK partials per row.
// Fully deterministic (no float atomics), graph-capturable, allocation-free.

#define NCHUNK 32
#define N_ROWS_MAX 64

__device__ float g_partials[N_ROWS_MAX * NCHUNK];

__global__ void __launch_bounds__(256) matvec_partial_kernel(
    const float* __restrict__ inp,
    const float* __restrict__ fc,
    int D)
{
    const int row   = blockIdx.y;
    const int chunk = blockIdx.x;
    const int vec_total = D / 4;                 // float4 count per row
    const int vec_per_chunk = vec_total / NCHUNK; // 8192 for D=1M

    const float4* __restrict__ a =
        reinterpret_cast<const float4*>(inp) + (size_t)chunk * vec_per_chunk;
    const float4* __restrict__ b =
        reinterpret_cast<const float4*>(fc + (size_t)row * D) + (size_t)chunk * vec_per_chunk;

    // 256 threads, vec_per_chunk/256 = 32 iterations. Two independent
    // accumulator pairs for ILP; loads are the real bottleneck (MLP via unroll).
    float s0 = 0.f, s1 = 0.f;
    int i = threadIdx.x;
    #pragma unroll 8
    for (; i < vec_per_chunk; i += 256) {
        float4 av = a[i];
        float4 bv = b[i];
        s0 = fmaf(av.x, bv.x, s0);
        s1 = fmaf(av.y, bv.y, s1);
        s0 = fmaf(av.z, bv.z, s0);
        s1 = fmaf(av.w, bv.w, s1);
    }
    float s = s0 + s1;

    // Block reduction: warp shuffle, then cross-warp via shared.
    __shared__ float warp_sums[8];
    #pragma unroll
    for (int off = 16; off > 0; off >>= 1)
        s += __shfl_down_sync(0xFFFFFFFFu, s, off);
    if ((threadIdx.x & 31) == 0)
        warp_sums[threadIdx.x >> 5] = s;
    __syncthreads();
    if (threadIdx.x < 8) {
        float v = warp_sums[threadIdx.x];
        #pragma unroll
        for (int off = 4; off > 0; off >>= 1)
            v += __shfl_down_sync(0xFFu, v, off);
        if (threadIdx.x == 0)
            g_partials[row * NCHUNK + chunk] = v;
    }
}

__global__ void matvec_finish_kernel(float* __restrict__ out)
{
    // One block per row, 32 threads = NCHUNK partials.
    const int row = blockIdx.x;
    float v = g_partials[row * NCHUNK + threadIdx.x];
    #pragma unroll
    for (int off = 16; off > 0; off >>= 1)
        v += __shfl_down_sync(0xFFFFFFFFu, v, off);
    if (threadIdx.x == 0)
        out[row] = v;
}

extern "C" void kernel_launch(void* const* d_in, const int* in_sizes, int n_in,
                              void* d_out, int out_size)
{
    const float* inp = (const float*)d_in[0];   // [D]
    const float* fc  = (const float*)d_in[1];   // [N_ROWS, D]
    float* out       = (float*)d_out;           // [N_ROWS]

    const int D      = in_sizes[0];
    const int n_rows = out_size;                // 50

    dim3 grid(NCHUNK, n_rows);
    matvec_partial_kernel<<<grid, 256>>>(inp, fc, D);
    matvec_finish_kernel<<<n_rows, 32>>>(out);
}

// round 2
// speedup vs baseline: 1.0812x; 1.0812x over previous
#include <cuda_runtime.h>
#include <cuda_bf16.h>

// Matvec: out[n] = sum_d fc[n][d] * input[d],  n < 50, d = 1048576.
// DRAM-bound: 200 MB of fc streamed once; 4 MB input stays L2-resident.
//
// Single fused kernel: grid (NCHUNK x N_ROWS). Each block reduces a
// contiguous chunk of one row into g_partials[row][chunk]; the LAST block to
// finish a row (threadfence-reduction pattern) sums that row's NCHUNK
// partials and writes out[row]. Deterministic: the final per-row summation
// has a fixed order; the int atomic is only an arrival counter.
// Counters are reset by the finishing block -> graph replays stay correct.

#define NCHUNK 64
#define N_ROWS_MAX 64

__device__ float g_partials[N_ROWS_MAX * NCHUNK];
__device__ int   g_arrive[N_ROWS_MAX];            // zero-initialized

__global__ void __launch_bounds__(256) matvec_fused_kernel(
    const float* __restrict__ inp,
    const float* __restrict__ fc,
    float* __restrict__ out,
    int D)
{
    const int row   = blockIdx.y;
    const int chunk = blockIdx.x;
    const int vec_per_chunk = (D / 4) / NCHUNK;   // 4096 for D=1M

    const float4* __restrict__ a =
        reinterpret_cast<const float4*>(inp) + (size_t)chunk * vec_per_chunk;
    const float4* __restrict__ b =
        reinterpret_cast<const float4*>(fc + (size_t)row * D) + (size_t)chunk * vec_per_chunk;

    // 256 threads x 16 iterations of float4. fc is streamed (evict-first,
    // __ldcs) so it doesn't flush the L2-resident input vector.
    float s0 = 0.f, s1 = 0.f;
    #pragma unroll 8
    for (int i = threadIdx.x; i < vec_per_chunk; i += 256) {
        float4 av = __ldg(a + i);
        float4 bv = __ldcs(b + i);
        s0 = fmaf(av.x, bv.x, s0);
        s1 = fmaf(av.y, bv.y, s1);
        s0 = fmaf(av.z, bv.z, s0);
        s1 = fmaf(av.w, bv.w, s1);
    }
    float s = s0 + s1;

    // Block reduction: warp shuffle, then cross-warp via shared.
    __shared__ float warp_sums[8];
    #pragma unroll
    for (int off = 16; off > 0; off >>= 1)
        s += __shfl_down_sync(0xFFFFFFFFu, s, off);
    if ((threadIdx.x & 31) == 0)
        warp_sums[threadIdx.x >> 5] = s;
    __syncthreads();

    __shared__ bool is_last;
    if (threadIdx.x == 0) {
        float v = 0.f;
        #pragma unroll
        for (int w = 0; w < 8; w++) v += warp_sums[w];
        g_partials[row * NCHUNK + chunk] = v;
        __threadfence();
        int old = atomicAdd(&g_arrive[row], 1);
        is_last = (old == NCHUNK - 1);
    }
    __syncthreads();

    // Last block for this row: reduce the NCHUNK partials deterministically.
    if (is_last && threadIdx.x < 32) {
        __threadfence();          // acquire: make all partials visible
        const float* p = &g_partials[row * NCHUNK];
        float v = 0.f;
        #pragma unroll
        for (int k = 0; k < NCHUNK / 32; k++)
            v += p[threadIdx.x + k * 32];
        #pragma unroll
        for (int off = 16; off > 0; off >>= 1)
            v += __shfl_down_sync(0xFFFFFFFFu, v, off);
        if (threadIdx.x == 0) {
            out[row] = v;
            g_arrive[row] = 0;    // reset for next graph replay
        }
    }
}

extern "C" void kernel_launch(void* const* d_in, const int* in_sizes, int n_in,
                              void* d_out, int out_size)
{
    const float* inp = (const float*)d_in[0];   // [D]
    const float* fc  = (const float*)d_in[1];   // [N_ROWS, D]
    float* out       = (float*)d_out;           // [N_ROWS]

    const int D      = in_sizes[0];
    const int n_rows = out_size;                // 50

    dim3 grid(NCHUNK, n_rows);
    matvec_fused_kernel<<<grid, 256>>>(inp, fc, out, D);
}